// round 3
// baseline (speedup 1.0000x reference)
#include <cuda_runtime.h>
#include <cuda_bf16.h>

// out[t, e] = cos(t) * s[e] + b[e],  s[e] = sum_q W[e,q]
// E = 1024 (b element count), T = out_size / E, Q = W_count / E.
// One block = 256 threads; thread tid owns embed columns [4*tid, 4*tid+4),
// holds s/b in registers, grid-strides over t, one float4 store per t.
__global__ __launch_bounds__(256, 8)
void pequant_kernel(const float* __restrict__ W,
                    const float* __restrict__ b,
                    float* __restrict__ out,
                    int T, int E, int Q) {
    const int tid = threadIdx.x;          // 0..255
    const int e0  = tid * 4;

    // Per-thread constants: s[j] = sum_q W[e0+j, q], bb[j] = b[e0+j]
    float s[4], bb[4];
#pragma unroll
    for (int j = 0; j < 4; j++) {
        const int e = e0 + j;
        float acc = 0.0f;
        const float* wr = W + (size_t)e * Q;
#pragma unroll 8
        for (int q = 0; q < Q; q++) acc += wr[q];
        s[j]  = acc;
        bb[j] = b[e];
    }

    // Grid-stride over timesteps; each block writes one full contiguous
    // 1024-float row per iteration (256 lanes x float4).
    for (int t = blockIdx.x; t < T; t += gridDim.x) {
        const float c = cosf((float)t);
        float4 v;
        v.x = fmaf(c, s[0], bb[0]);
        v.y = fmaf(c, s[1], bb[1]);
        v.z = fmaf(c, s[2], bb[2]);
        v.w = fmaf(c, s[3], bb[3]);
        *reinterpret_cast<float4*>(out + (size_t)t * E + e0) = v;
    }
}

extern "C" void kernel_launch(void* const* d_in, const int* in_sizes, int n_in,
                              void* d_out, int out_size) {
    // metadata order: x (unused), W [E, Q], b [E]
    const float* W = (const float*)d_in[1];
    const float* b = (const float*)d_in[2];
    float* out = (float*)d_out;

    const int E = in_sizes[2];            // 1024
    const int Q = in_sizes[1] / E;        // 8
    const int T = out_size / E;           // 65536

    const int threads = E / 4;            // 256
    int blocks = 2048;                    // ~13.8 waves on 148 SMs @8 blocks/SM
    if (blocks > T) blocks = T;

    pequant_kernel<<<blocks, threads>>>(W, b, out, T, E, Q);
}

// round 7
// speedup vs baseline: 1.2371x; 1.2371x over previous
#include <cuda_runtime.h>
#include <cuda_bf16.h>

// out[t, e] = cos(t) * s[e] + b[e],  s[e] = sum_q W[e,q]
// E = 1024, T = out_size / E.
//
// R0 profile: per-thread STG path (l1tex) binding at 79% while DRAM sat at
// 32%. This version stages RPC=4 rows (16 KB) in SMEM and drains them with
// cp.async.bulk (async-proxy SMEM->L2 bulk store), double-buffered with
// bulk_group backpressure, bypassing the L1 per-thread store path entirely.
// (Resubmission of R3 — that bench died to a broker infra failure, untested.)

#define RPC 4          // rows per bulk group (4 x 4KB = 16KB)
#define EROW 1024      // embed dim (compile-time for smem layout; checked at launch)

__global__ __launch_bounds__(256)
void pequant_bulk_kernel(const float* __restrict__ W,
                         const float* __restrict__ b,
                         float* __restrict__ out,
                         int T, int Q) {
    __shared__ __align__(128) float buf[2][RPC * EROW];   // 32 KB

    const int tid = threadIdx.x;          // 0..255
    const int e0  = tid * 4;

    // Per-thread row constants: s[j] = sum_q W[e0+j, q], bb[j] = b[e0+j].
    float s[4], bb[4];
#pragma unroll
    for (int j = 0; j < 4; j++) {
        const int e = e0 + j;
        float acc = 0.0f;
        const float* wr = W + (size_t)e * Q;
#pragma unroll 8
        for (int q = 0; q < Q; q++) acc += __ldg(wr + q);
        s[j]  = acc;
        bb[j] = __ldg(b + e);
    }

    const unsigned sm0 = (unsigned)__cvta_generic_to_shared(&buf[0][0]);
    const unsigned sm1 = (unsigned)__cvta_generic_to_shared(&buf[1][0]);

    const int stride = gridDim.x * RPC;
    int k = 0;
    for (int base = blockIdx.x * RPC; base < T; base += stride, ++k) {
        const int ph = k & 1;

        // Reuse buffer ph only after its bulk store (issued 2 iterations ago)
        // has finished READING smem. Allow 1 group (last iter's) in flight.
        if (k >= 2 && tid == 0)
            asm volatile("cp.async.bulk.wait_group.read 1;" ::: "memory");
        __syncthreads();

        const int rows = min(RPC, T - base);
        float* bp = buf[ph];
#pragma unroll
        for (int r = 0; r < RPC; r++) {
            if (r < rows) {
                const float c = cosf((float)(base + r));
                float4 v;
                v.x = fmaf(c, s[0], bb[0]);
                v.y = fmaf(c, s[1], bb[1]);
                v.z = fmaf(c, s[2], bb[2]);
                v.w = fmaf(c, s[3], bb[3]);
                *reinterpret_cast<float4*>(bp + r * EROW + e0) = v;
            }
        }
        __syncthreads();

        if (tid == 0) {
            // Order this CTA's generic-proxy STS before the async-proxy read.
            asm volatile("fence.proxy.async.shared::cta;" ::: "memory");
            const unsigned src = ph ? sm1 : sm0;
            asm volatile(
                "cp.async.bulk.global.shared::cta.bulk_group [%0], [%1], %2;"
                :: "l"(out + (size_t)base * EROW), "r"(src),
                   "r"(rows * (EROW * 4))
                : "memory");
            asm volatile("cp.async.bulk.commit_group;" ::: "memory");
        }
    }

    // Drain all outstanding bulk stores before exit.
    if (tid == 0)
        asm volatile("cp.async.bulk.wait_group 0;" ::: "memory");
}

// Fallback (R0-style direct STG) for the E != 1024 case — never expected here.
__global__ __launch_bounds__(256, 8)
void pequant_fallback_kernel(const float* __restrict__ W,
                             const float* __restrict__ b,
                             float* __restrict__ out,
                             int T, int E, int Q) {
    const int tid = threadIdx.x;
    const int e0  = tid * 4;
    float s[4], bb[4];
#pragma unroll
    for (int j = 0; j < 4; j++) {
        const int e = e0 + j;
        float acc = 0.0f;
        const float* wr = W + (size_t)e * Q;
        for (int q = 0; q < Q; q++) acc += wr[q];
        s[j]  = acc;
        bb[j] = b[e];
    }
    for (int t = blockIdx.x; t < T; t += gridDim.x) {
        const float c = cosf((float)t);
        float4 v;
        v.x = fmaf(c, s[0], bb[0]);
        v.y = fmaf(c, s[1], bb[1]);
        v.z = fmaf(c, s[2], bb[2]);
        v.w = fmaf(c, s[3], bb[3]);
        *reinterpret_cast<float4*>(out + (size_t)t * E + e0) = v;
    }
}

extern "C" void kernel_launch(void* const* d_in, const int* in_sizes, int n_in,
                              void* d_out, int out_size) {
    // metadata order: x (unused), W [E, Q], b [E]
    const float* W = (const float*)d_in[1];
    const float* b = (const float*)d_in[2];
    float* out = (float*)d_out;

    const int E = in_sizes[2];            // 1024
    const int Q = in_sizes[1] / E;        // 8
    const int T = out_size / E;           // 65536

    if (E == EROW) {
        const int chunks = (T + RPC - 1) / RPC;   // 16384
        int blocks = 148 * 6;                      // grid-stride; occupancy-agnostic
        if (blocks > chunks) blocks = chunks;
        pequant_bulk_kernel<<<blocks, EROW / 4>>>(W, b, out, T, Q);
    } else {
        int blocks = 2048;
        if (blocks > T) blocks = T;
        pequant_fallback_kernel<<<blocks, E / 4>>>(W, b, out, T, E, Q);
    }
}

// round 9
// speedup vs baseline: 1.3428x; 1.0854x over previous
#include <cuda_runtime.h>
#include <cuda_bf16.h>

// out[t, e] = cos(t) * s[e] + b[e],  s[e] = sum_q W[e,q]
// E = 1024, T = out_size / E.
//
// R7: everything sat at 40-50% (latency/serialization, not a throughput wall).
// Amortize the per-group handshake: RPC 4 -> 6 rows (24 KB bulk groups),
// 2 x 24 KB = 48 KB static smem (static limit), 1.5x fewer barriers per byte,
// 1.5x more bulk bytes in flight per CTA, 4 CTAs/SM.

#define RPC 6          // rows per bulk group (6 x 4KB = 24KB)
#define EROW 1024      // embed dim (compile-time for smem layout; checked at launch)

__global__ __launch_bounds__(256)
void pequant_bulk_kernel(const float* __restrict__ W,
                         const float* __restrict__ b,
                         float* __restrict__ out,
                         int T, int Q) {
    __shared__ __align__(128) float buf[2][RPC * EROW];   // 48 KB (static limit)

    const int tid = threadIdx.x;          // 0..255
    const int e0  = tid * 4;

    // Per-thread row constants: s[j] = sum_q W[e0+j, q], bb[j] = b[e0+j].
    float s[4], bb[4];
#pragma unroll
    for (int j = 0; j < 4; j++) {
        const int e = e0 + j;
        float acc = 0.0f;
        const float* wr = W + (size_t)e * Q;
#pragma unroll 8
        for (int q = 0; q < Q; q++) acc += __ldg(wr + q);
        s[j]  = acc;
        bb[j] = __ldg(b + e);
    }

    const unsigned sm0 = (unsigned)__cvta_generic_to_shared(&buf[0][0]);
    const unsigned sm1 = (unsigned)__cvta_generic_to_shared(&buf[1][0]);

    const int stride = gridDim.x * RPC;
    int k = 0;
    for (int base = blockIdx.x * RPC; base < T; base += stride, ++k) {
        const int ph = k & 1;

        // Reuse buffer ph only after its bulk store (issued 2 iterations ago)
        // finished READING smem. Group from last iteration may stay in flight.
        if (k >= 2 && tid == 0)
            asm volatile("cp.async.bulk.wait_group.read 1;" ::: "memory");
        __syncthreads();

        const int rows = min(RPC, T - base);
        float* bp = buf[ph];
        if (rows == RPC) {
            // Hot path: fully unrolled 6-row fill, STS batch issues back-to-back.
#pragma unroll
            for (int r = 0; r < RPC; r++) {
                const float c = cosf((float)(base + r));
                float4 v;
                v.x = fmaf(c, s[0], bb[0]);
                v.y = fmaf(c, s[1], bb[1]);
                v.z = fmaf(c, s[2], bb[2]);
                v.w = fmaf(c, s[3], bb[3]);
                *reinterpret_cast<float4*>(bp + r * EROW + e0) = v;
            }
        } else {
            for (int r = 0; r < rows; r++) {
                const float c = cosf((float)(base + r));
                float4 v;
                v.x = fmaf(c, s[0], bb[0]);
                v.y = fmaf(c, s[1], bb[1]);
                v.z = fmaf(c, s[2], bb[2]);
                v.w = fmaf(c, s[3], bb[3]);
                *reinterpret_cast<float4*>(bp + r * EROW + e0) = v;
            }
        }
        __syncthreads();

        if (tid == 0) {
            // Order this CTA's generic-proxy STS before the async-proxy read.
            asm volatile("fence.proxy.async.shared::cta;" ::: "memory");
            const unsigned src = ph ? sm1 : sm0;
            asm volatile(
                "cp.async.bulk.global.shared::cta.bulk_group [%0], [%1], %2;"
                :: "l"(out + (size_t)base * EROW), "r"(src),
                   "r"(rows * (EROW * 4))
                : "memory");
            asm volatile("cp.async.bulk.commit_group;" ::: "memory");
        }
    }

    // Drain all outstanding bulk stores before exit.
    if (tid == 0)
        asm volatile("cp.async.bulk.wait_group 0;" ::: "memory");
}

// Fallback (direct STG) for the E != 1024 case — never expected here.
__global__ __launch_bounds__(256, 8)
void pequant_fallback_kernel(const float* __restrict__ W,
                             const float* __restrict__ b,
                             float* __restrict__ out,
                             int T, int E, int Q) {
    const int tid = threadIdx.x;
    const int e0  = tid * 4;
    float s[4], bb[4];
#pragma unroll
    for (int j = 0; j < 4; j++) {
        const int e = e0 + j;
        float acc = 0.0f;
        const float* wr = W + (size_t)e * Q;
        for (int q = 0; q < Q; q++) acc += wr[q];
        s[j]  = acc;
        bb[j] = b[e];
    }
    for (int t = blockIdx.x; t < T; t += gridDim.x) {
        const float c = cosf((float)t);
        float4 v;
        v.x = fmaf(c, s[0], bb[0]);
        v.y = fmaf(c, s[1], bb[1]);
        v.z = fmaf(c, s[2], bb[2]);
        v.w = fmaf(c, s[3], bb[3]);
        *reinterpret_cast<float4*>(out + (size_t)t * E + e0) = v;
    }
}

extern "C" void kernel_launch(void* const* d_in, const int* in_sizes, int n_in,
                              void* d_out, int out_size) {
    // metadata order: x (unused), W [E, Q], b [E]
    const float* W = (const float*)d_in[1];
    const float* b = (const float*)d_in[2];
    float* out = (float*)d_out;

    const int E = in_sizes[2];            // 1024
    const int Q = in_sizes[1] / E;        // 8
    const int T = out_size / E;           // 65536

    if (E == EROW) {
        const int chunks = (T + RPC - 1) / RPC;   // 10923
        int blocks = 148 * 4;                      // 4 CTAs/SM @ 48 KB smem
        if (blocks > chunks) blocks = chunks;
        pequant_bulk_kernel<<<blocks, EROW / 4>>>(W, b, out, T, Q);
    } else {
        int blocks = 2048;
        if (blocks > T) blocks = T;
        pequant_fallback_kernel<<<blocks, E / 4>>>(W, b, out, T, E, Q);
    }
}